// round 15
// baseline (speedup 1.0000x reference)
#include <cuda_runtime.h>
#include <cuda_fp16.h>
#include <cstdint>

#define B_S   256
#define P_N   64
#define V_N   2562
#define KP    256           // K' = 192 (fp16) + trans chunk (cols 192/193)
#define M_T   128           // v rows per CTA
#define N_T   128           // n cols per CTA (one i, half the bs)
#define NROT  128           // rot blocks (2 bs each)
#define PL    16384u        // one 64-col plane: 128 rows x 128B

// ---- scratch (zero-initialized device global; no runtime alloc) ----
__device__ __align__(16) __half g_B[(size_t)3 * B_S * KP];    // ~0.4MB

__device__ __forceinline__ uint32_t smem_u32(const void* p) {
    uint32_t a;
    asm("{ .reg .u64 t; cvta.to.shared.u64 t, %1; cvt.u32.u64 %0, t; }" : "=r"(a) : "l"(p));
    return a;
}
__device__ __forceinline__ uint32_t sw128(uint32_t x) { return x ^ ((x >> 3) & 0x70); }

#define CP16(dst, src) \
    asm volatile("cp.async.cg.shared.global [%0], [%1], 16;" :: "r"(dst), "l"(src))
#define CP_COMMIT() asm volatile("cp.async.commit_group;" ::: "memory")
#define CP_WAIT0()  asm volatile("cp.async.wait_group 0;" ::: "memory")

#define LDSM4(r, addr) \
    asm volatile("ldmatrix.sync.aligned.m8n8.x4.shared.b16 {%0,%1,%2,%3}, [%4];" \
        : "=r"((r)[0]), "=r"((r)[1]), "=r"((r)[2]), "=r"((r)[3]) : "r"(addr))

#define MMA(d, a, b0, b1) \
    asm volatile("mma.sync.aligned.m16n8k16.row.col.f32.f16.f16.f32 " \
        "{%0,%1,%2,%3}, {%4,%5,%6,%7}, {%8,%9}, {%0,%1,%2,%3};" \
        : "+f"((d)[0]), "+f"((d)[1]), "+f"((d)[2]), "+f"((d)[3]) \
        : "r"((a)[0]), "r"((a)[1]), "r"((a)[2]), "r"((a)[3]), "r"(b0), "r"(b1))

// ---------------------------------------------------------------------------
// Prep: B-hat rows. 2 bs per block. Row (i,bs): cols 0..191 = m[i][j]*w*s
// packed k=p*3+j; cols 192/193 = trans hi/lo; 194..255 stay zero (static init).
// ---------------------------------------------------------------------------
__global__ __launch_bounds__(128) void rot_kernel(
    const float* __restrict__ scales,
    const float* __restrict__ transforms,
    const float* __restrict__ pw)
{
    __shared__ float red[128][4];
    const int tid = threadIdx.x;
    const int bs = blockIdx.x * 2 + (tid >> 6);
    const int p  = tid & 63;

    const float* t = transforms + ((size_t)bs * P_N + p) * 6;
    const float w  = pw[bs * P_N + p];
    const float ws = w * scales[bs];

    float sx, cx, sy, cy, sz, cz;
    sincosf(t[3], &sx, &cx);
    sincosf(t[4], &sy, &cy);
    sincosf(t[5], &sz, &cz);

    float m[9];
    m[0] = cy*cz;            m[1] = -cy*sz;           m[2] = sy;
    m[3] = cx*sz + sx*sy*cz; m[4] = cx*cz - sx*sy*sz; m[5] = -sx*cy;
    m[6] = sx*sz - cx*sy*cz; m[7] = sx*cz + cx*sy*sz; m[8] = cx*cy;

    #pragma unroll
    for (int i = 0; i < 3; ++i) {
        __half* row = g_B + ((size_t)i * B_S + bs) * KP;
        #pragma unroll
        for (int j = 0; j < 3; ++j)
            row[p * 3 + j] = __float2half(m[i * 3 + j] * ws);
    }

    red[tid][0] = w * t[0];
    red[tid][1] = w * t[1];
    red[tid][2] = w * t[2];
    __syncthreads();
    if (p < 3) {
        const int b0 = (tid >> 6) * 64;
        float s = 0.f;
        for (int q = 0; q < 64; ++q) s += red[b0 + q][p];
        const __half hi = __float2half(s);
        const __half lo = __float2half(s - __half2float(hi));
        __half* row = g_B + ((size_t)p * B_S + bs) * KP;
        row[192] = hi; row[193] = lo;
    }
}

// ---------------------------------------------------------------------------
// Fused A-prep + GEMM. Per CTA (128 v x 128 n, one i-component):
//  - cp.async the full B tile (4 planes, 64KB) from g_B
//  - build A tile in smem directly from off/base (fp16 convert + transpose)
//  - one barrier, then 16 back-to-back ldmatrix/MMA k-steps, no chunk syncs
// smem: A planes [0,64KB), B planes [64KB,128KB), s_base floats at 128KB.
// ---------------------------------------------------------------------------
#define A_OFF 0u
#define B_OFF 65536u
#define BASE_OFF 131072u
#define SMEM_BYTES (131072 + 1664)

__global__ __launch_bounds__(512, 1) void mesh_gemm_kernel(
    const float* __restrict__ off,    // (P,V,3)
    const float* __restrict__ base,   // (V,3)
    float* __restrict__ out)          // (B*S, V, 3)
{
    extern __shared__ __align__(1024) char smem[];
    const uint32_t sbase = smem_u32(smem);
    const int tid  = threadIdx.x;
    const int lane = tid & 31;
    const int warp = tid >> 5;                 // 0..15
    const int v0   = blockIdx.x * M_T;
    const int nb   = blockIdx.y;
    const int i_   = nb >> 1;                  // output component (0..2)
    const int bs0  = (nb & 1) * N_T;           // bs half base
    const int bRow0 = i_ * B_S + bs0;          // g_B row base

    // ---- 1) launch B tile cp.async (4 planes x 128 rows x 128B) ----
    {
        const int sRow = tid >> 3, sU = (tid & 7) * 16;   // 64 rows per pass
        #pragma unroll
        for (int c = 0; c < 4; ++c) {
            #pragma unroll
            for (int it = 0; it < 2; ++it) {
                const int row = sRow + it * 64;
                CP16(sbase + B_OFF + c * PL + sw128(row * 128 + sU),
                     g_B + ((size_t)(bRow0 + row) * KP + c * 64) + sU / 2);
            }
        }
        CP_COMMIT();
    }

    // ---- 2) stage base slice + zero A plane 3 ----
    float* s_base = (float*)(smem + BASE_OFF);            // [384]
    {
        if (tid < 384)
            s_base[tid] = (v0 * 3 + tid < V_N * 3) ? base[v0 * 3 + tid] : 0.f;
        // zero A plane 3 (trans chunk): 1024 uint4
        #pragma unroll
        for (int it = 0; it < 2; ++it)
            *(uint4*)(smem + A_OFF + 3 * PL + (tid + it * 512) * 16) = make_uint4(0,0,0,0);
    }
    __syncthreads();

    // ---- 3) A-prep: read off (coalesced float2 per p), +base, fp16, scatter ----
    {
        const int nv3 = min(M_T * 3, (V_N - v0) * 3);     // valid floats per p
        for (int idx = tid; idx < P_N * 192; idx += 512) {
            const int p = idx / 192, qq = idx - p * 192;
            const int f0 = 2 * qq;
            float e[2];
            if (f0 + 1 < nv3) {
                const float2 d = *(const float2*)(off + ((size_t)p * V_N + v0) * 3 + f0);
                e[0] = d.x; e[1] = d.y;
            } else {
                e[0] = (f0 < nv3) ? off[((size_t)p * V_N + v0) * 3 + f0] : 0.f;
                e[1] = 0.f;
            }
            #pragma unroll
            for (int t = 0; t < 2; ++t) {
                const int f = f0 + t;
                const int vl = f / 3, j = f - 3 * vl;
                const int k = p * 3 + j;
                const uint32_t addr = A_OFF + (uint32_t)(k >> 6) * PL
                                    + sw128(vl * 128 + (k & 63) * 2);
                *(__half*)(smem + addr) = __float2half(e[t] + s_base[f]);
            }
        }
        // trans-chunk ones: A plane 3 cols 0,1 = 1.0
        if (tid < M_T) {
            const __half one = __float2half(1.0f);
            const uint32_t addr = A_OFF + 3 * PL + sw128(tid * 128);
            *(__half*)(smem + addr) = one;
            *(__half*)(smem + addr + 2) = one;
        }
    }

    CP_WAIT0();
    __syncthreads();

    // ---- 4) compute: 4 planes x 4 k-steps, no syncs ----
    const int wm = warp & 3;                   // warp row (4) -> 32 v
    const int wn = warp >> 2;                  // warp col (4) -> 32 n
    const int rowA  = wm * 32 + (lane & 7) + ((lane >> 3) & 1) * 8;
    const int kselA = ((lane >> 4) & 1) * 16;
    const int rowB  = wn * 32 + ((lane >> 4) & 1) * 8 + (lane & 7);
    const int kselB = ((lane >> 3) & 1) * 16;

    float acc[2][4][4];
    #pragma unroll
    for (int mt = 0; mt < 2; ++mt)
        #pragma unroll
        for (int nt = 0; nt < 4; ++nt)
            #pragma unroll
            for (int e = 0; e < 4; ++e) acc[mt][nt][e] = 0.f;

    #pragma unroll
    for (int c = 0; c < 4; ++c) {
        const uint32_t sA = sbase + A_OFF + c * PL;
        const uint32_t sB = sbase + B_OFF + c * PL;
        #pragma unroll
        for (int ks = 0; ks < 4; ++ks) {
            uint32_t a0[4], a1[4], q0[4], q1[4];
            LDSM4(a0, sA + sw128(rowA * 128 + ks * 32 + kselA));
            LDSM4(a1, sA + sw128((rowA + 16) * 128 + ks * 32 + kselA));
            LDSM4(q0, sB + sw128(rowB * 128 + ks * 32 + kselB));
            LDSM4(q1, sB + sw128((rowB + 16) * 128 + ks * 32 + kselB));
            MMA(acc[0][0], a0, q0[0], q0[1]);  MMA(acc[0][1], a0, q0[2], q0[3]);
            MMA(acc[0][2], a0, q1[0], q1[1]);  MMA(acc[0][3], a0, q1[2], q1[3]);
            MMA(acc[1][0], a1, q0[0], q0[1]);  MMA(acc[1][1], a1, q0[2], q0[3]);
            MMA(acc[1][2], a1, q1[0], q1[1]);  MMA(acc[1][3], a1, q1[2], q1[3]);
        }
    }

    // ---- 5) epilogue: scatter stores ----
    const int g  = lane >> 2;
    const int cq = lane & 3;
    #pragma unroll
    for (int mt = 0; mt < 2; ++mt) {
        const int vA = v0 + wm * 32 + mt * 16 + g;
        const int vB = vA + 8;
        #pragma unroll
        for (int nt = 0; nt < 4; ++nt) {
            const int bs = bs0 + wn * 32 + nt * 8 + 2 * cq;
            const size_t r0 = ((size_t)bs * V_N) * 3 + i_;
            const size_t r1 = ((size_t)(bs + 1) * V_N) * 3 + i_;
            if (vA < V_N) {
                out[r0 + (size_t)vA * 3] = acc[mt][nt][0];
                out[r1 + (size_t)vA * 3] = acc[mt][nt][1];
            }
            if (vB < V_N) {
                out[r0 + (size_t)vB * 3] = acc[mt][nt][2];
                out[r1 + (size_t)vB * 3] = acc[mt][nt][3];
            }
        }
    }
}

// ---------------------------------------------------------------------------
extern "C" void kernel_launch(void* const* d_in, const int* in_sizes, int n_in,
                              void* d_out, int out_size)
{
    (void)in_sizes; (void)n_in; (void)out_size;
    const float* scales     = (const float*)d_in[0];  // (B,S,1)
    const float* transforms = (const float*)d_in[1];  // (B,S,P,6)
    const float* pw         = (const float*)d_in[2];  // (B,S,P)
    const float* off        = (const float*)d_in[3];  // (P,V,3)
    const float* base       = (const float*)d_in[4];  // (V,3)
    float* out = (float*)d_out;

    rot_kernel<<<NROT, 128>>>(scales, transforms, pw);

    cudaFuncSetAttribute(mesh_gemm_kernel,
                         cudaFuncAttributeMaxDynamicSharedMemorySize, SMEM_BYTES);
    dim3 grid((V_N + M_T - 1) / M_T, 6);   // (21, 6) = 126 CTAs, 1 per SM
    mesh_gemm_kernel<<<grid, 512, SMEM_BYTES>>>(off, base, out);
}

// round 16
// speedup vs baseline: 1.2224x; 1.2224x over previous
#include <cuda_runtime.h>
#include <cuda_fp16.h>
#include <cstdint>

#define B_S   256
#define P_N   64
#define V_N   2562
#define VPAD  2688          // 21*128, zero-padded tail rows
#define KP    256           // K' = 192 (fp16) + trans chunk (cols 192/193)
#define M_T   128
#define N_T   128
#define VTP   16            // defsplit v-tile
#define NDEF  161           // ceil(2562/16)
#define NROT  128           // rot blocks (2 bs each)
#define ROWS2 264           // padded prep staging row stride (fp16)
#define PL    16384u        // one 64-col plane: 128 rows x 128B

// ---- scratch (zero-initialized device globals; no runtime alloc) ----
__device__ __align__(16) __half g_def[(size_t)VPAD * KP];     // ~1.4MB
__device__ __align__(16) __half g_B[(size_t)3 * B_S * KP];    // ~0.4MB

__device__ __forceinline__ uint32_t smem_u32(const void* p) {
    uint32_t a;
    asm("{ .reg .u64 t; cvta.to.shared.u64 t, %1; cvt.u32.u64 %0, t; }" : "=r"(a) : "l"(p));
    return a;
}
__device__ __forceinline__ uint32_t sw128(uint32_t x) { return x ^ ((x >> 3) & 0x70); }

#define CP16(dst, src) \
    asm volatile("cp.async.cg.shared.global [%0], [%1], 16;" :: "r"(dst), "l"(src))
#define CP_COMMIT() asm volatile("cp.async.commit_group;" ::: "memory")
#define CP_WAIT0()  asm volatile("cp.async.wait_group 0;" ::: "memory")

#define LDSM4(r, addr) \
    asm volatile("ldmatrix.sync.aligned.m8n8.x4.shared.b16 {%0,%1,%2,%3}, [%4];" \
        : "=r"((r)[0]), "=r"((r)[1]), "=r"((r)[2]), "=r"((r)[3]) : "r"(addr))

#define MMA(d, a, b0, b1) \
    asm volatile("mma.sync.aligned.m16n8k16.row.col.f32.f16.f16.f32 " \
        "{%0,%1,%2,%3}, {%4,%5,%6,%7}, {%8,%9}, {%0,%1,%2,%3};" \
        : "+f"((d)[0]), "+f"((d)[1]), "+f"((d)[2]), "+f"((d)[3]) \
        : "r"((a)[0]), "r"((a)[1]), "r"((a)[2]), "r"((a)[3]), "r"(b0), "r"(b1))

// ---------------------------------------------------------------------------
// Fused prep (round-14 version). Blocks [0,NDEF): defsplit; rest: rot.
// ---------------------------------------------------------------------------
#define PREP_SMEM (VTP * ROWS2 * 2 + 256)

__global__ __launch_bounds__(128) void prep_kernel(
    const float* __restrict__ off,
    const float* __restrict__ base,
    const float* __restrict__ scales,
    const float* __restrict__ transforms,
    const float* __restrict__ pw)
{
    extern __shared__ __align__(16) char smem[];
    const int tid = threadIdx.x;

    if (blockIdx.x < NDEF) {
        __half* s_row = (__half*)smem;                      // [VTP][ROWS2]
        float* s_base = (float*)(smem + VTP * ROWS2 * 2);   // [48]
        const int v0 = blockIdx.x * VTP;
        const int nv3 = min(VTP * 3, (V_N - v0) * 3);

        for (int i = tid; i < (VTP * ROWS2) / 8; i += 128)
            ((uint4*)s_row)[i] = make_uint4(0, 0, 0, 0);
        if (tid < VTP * 3)
            s_base[tid] = (v0 * 3 + tid < V_N * 3) ? base[v0 * 3 + tid] : 0.f;
        __syncthreads();

        for (int idx = tid; idx < P_N * 24; idx += 128) {
            const int p = idx / 24, q = idx - p * 24;
            const int f0 = 2 * q;
            float e[2];
            if (f0 + 1 < nv3) {
                const float2 d = *(const float2*)(off + ((size_t)p * V_N + v0) * 3 + f0);
                e[0] = d.x; e[1] = d.y;
            } else {
                e[0] = (f0 < nv3) ? off[((size_t)p * V_N + v0) * 3 + f0] : 0.f;
                e[1] = 0.f;
            }
            #pragma unroll
            for (int t = 0; t < 2; ++t) {
                const int f = f0 + t;
                const int vl = f / 3, j = f - 3 * vl;
                s_row[vl * ROWS2 + p * 3 + j] = __float2half(e[t] + s_base[f]);
            }
        }
        if (tid < VTP) {
            s_row[tid * ROWS2 + 192] = __float2half(1.0f);
            s_row[tid * ROWS2 + 193] = __float2half(1.0f);
        }
        __syncthreads();

        for (int i = tid; i < VTP * 32; i += 128) {
            const int row = i >> 5, u = i & 31;
            *(uint4*)(g_def + (size_t)(v0 + row) * KP + u * 8) =
                ((const uint4*)(s_row + row * ROWS2))[u];
        }
    } else {
        const int bs = (blockIdx.x - NDEF) * 2 + (tid >> 6);
        const int p  = tid & 63;

        const float* t = transforms + ((size_t)bs * P_N + p) * 6;
        const float w  = pw[bs * P_N + p];
        const float ws = w * scales[bs];

        float sx, cx, sy, cy, sz, cz;
        sincosf(t[3], &sx, &cx);
        sincosf(t[4], &sy, &cy);
        sincosf(t[5], &sz, &cz);

        float m[9];
        m[0] = cy*cz;            m[1] = -cy*sz;           m[2] = sy;
        m[3] = cx*sz + sx*sy*cz; m[4] = cx*cz - sx*sy*sz; m[5] = -sx*cy;
        m[6] = sx*sz - cx*sy*cz; m[7] = sx*cz + cx*sy*sz; m[8] = cx*cy;

        #pragma unroll
        for (int i = 0; i < 3; ++i) {
            __half* row = g_B + ((size_t)i * B_S + bs) * KP;
            #pragma unroll
            for (int j = 0; j < 3; ++j)
                row[p * 3 + j] = __float2half(m[i * 3 + j] * ws);
        }

        float* red = (float*)smem;   // [128][4]
        red[tid * 4 + 0] = w * t[0];
        red[tid * 4 + 1] = w * t[1];
        red[tid * 4 + 2] = w * t[2];
        __syncthreads();
        if (p < 3) {
            const int b0 = (tid >> 6) * 64;
            float s = 0.f;
            for (int q = 0; q < 64; ++q) s += red[(b0 + q) * 4 + p];
            const __half hi = __float2half(s);
            const __half lo = __float2half(s - __half2float(hi));
            __half* row = g_B + ((size_t)p * B_S + bs) * KP;
            row[192] = hi; row[193] = lo;
        }
    }
}

// ---------------------------------------------------------------------------
// GEMM, single-shot: cp.async all 4 A planes + 4 B planes (128KB), one wait,
// 16 back-to-back k-steps, then smem-transposed epilogue with lane=v stores
// (12 sectors/warp-store instead of 32). Grid (21,6) = 126 CTAs, 1/SM.
// ---------------------------------------------------------------------------
#define A_OFF 0u
#define B_OFF 65536u
#define SMEM_BYTES 131072
#define OPAD  132           // s_out row stride in floats

__global__ __launch_bounds__(512, 1) void mesh_gemm_kernel(float* __restrict__ out)
{
    extern __shared__ __align__(1024) char smem[];
    const uint32_t sbase = smem_u32(smem);
    const int tid  = threadIdx.x;
    const int lane = tid & 31;
    const int warp = tid >> 5;                 // 0..15
    const int v0   = blockIdx.x * M_T;
    const int nb   = blockIdx.y;
    const int i_   = nb >> 1;                  // output component (0..2)
    const int bs0  = (nb & 1) * N_T;
    const int bRow0 = i_ * B_S + bs0;

    // ---- 1) single-shot load: A planes from g_def, B planes from g_B ----
    {
        const int sRow = tid >> 3, sU = (tid & 7) * 16;
        #pragma unroll
        for (int c = 0; c < 4; ++c) {
            #pragma unroll
            for (int it = 0; it < 2; ++it) {
                const int row = sRow + it * 64;
                CP16(sbase + A_OFF + c * PL + sw128(row * 128 + sU),
                     g_def + ((size_t)(v0 + row) * KP + c * 64) + sU / 2);
                CP16(sbase + B_OFF + c * PL + sw128(row * 128 + sU),
                     g_B + ((size_t)(bRow0 + row) * KP + c * 64) + sU / 2);
            }
        }
        CP_COMMIT();
    }
    CP_WAIT0();
    __syncthreads();

    // ---- 2) compute: 4 planes x 4 k-steps, no syncs ----
    const int wm = warp & 3;
    const int wn = warp >> 2;
    const int rowA  = wm * 32 + (lane & 7) + ((lane >> 3) & 1) * 8;
    const int kselA = ((lane >> 4) & 1) * 16;
    const int rowB  = wn * 32 + ((lane >> 4) & 1) * 8 + (lane & 7);
    const int kselB = ((lane >> 3) & 1) * 16;

    float acc[2][4][4];
    #pragma unroll
    for (int mt = 0; mt < 2; ++mt)
        #pragma unroll
        for (int nt = 0; nt < 4; ++nt)
            #pragma unroll
            for (int e = 0; e < 4; ++e) acc[mt][nt][e] = 0.f;

    #pragma unroll
    for (int c = 0; c < 4; ++c) {
        const uint32_t sA = sbase + A_OFF + c * PL;
        const uint32_t sB = sbase + B_OFF + c * PL;
        #pragma unroll
        for (int ks = 0; ks < 4; ++ks) {
            uint32_t a0[4], a1[4], q0[4], q1[4];
            LDSM4(a0, sA + sw128(rowA * 128 + ks * 32 + kselA));
            LDSM4(a1, sA + sw128((rowA + 16) * 128 + ks * 32 + kselA));
            LDSM4(q0, sB + sw128(rowB * 128 + ks * 32 + kselB));
            LDSM4(q1, sB + sw128((rowB + 16) * 128 + ks * 32 + kselB));
            MMA(acc[0][0], a0, q0[0], q0[1]);  MMA(acc[0][1], a0, q0[2], q0[3]);
            MMA(acc[0][2], a0, q1[0], q1[1]);  MMA(acc[0][3], a0, q1[2], q1[3]);
            MMA(acc[1][0], a1, q0[0], q0[1]);  MMA(acc[1][1], a1, q0[2], q0[3]);
            MMA(acc[1][2], a1, q1[0], q1[1]);  MMA(acc[1][3], a1, q1[2], q1[3]);
        }
    }
    __syncthreads();   // everyone done reading smem; safe to reuse as s_out

    // ---- 3) stage accs into s_out[bs][v] (fp32, OPAD row stride) ----
    float* s_out = (float*)smem;   // 128 x OPAD floats = 67.6KB
    {
        const int g  = lane >> 2;
        const int cq = lane & 3;
        #pragma unroll
        for (int mt = 0; mt < 2; ++mt) {
            const int vA = wm * 32 + mt * 16 + g;
            const int vB = vA + 8;
            #pragma unroll
            for (int nt = 0; nt < 4; ++nt) {
                const int bs = wn * 32 + nt * 8 + 2 * cq;   // local bs
                s_out[bs * OPAD + vA]       = acc[mt][nt][0];
                s_out[(bs + 1) * OPAD + vA] = acc[mt][nt][1];
                s_out[bs * OPAD + vB]       = acc[mt][nt][2];
                s_out[(bs + 1) * OPAD + vB] = acc[mt][nt][3];
            }
        }
    }
    __syncthreads();

    // ---- 4) stores: warp per bs row, lane = consecutive v (12 sectors/store) ----
    {
        const int nv = min(M_T, V_N - v0);
        #pragma unroll
        for (int r = 0; r < 8; ++r) {
            const int bsl = warp + r * 16;                 // local bs row
            const size_t obase = ((size_t)(bs0 + bsl) * V_N + v0) * 3 + i_;
            #pragma unroll
            for (int k = 0; k < 4; ++k) {
                const int vl = lane + k * 32;
                if (vl < nv)
                    out[obase + (size_t)vl * 3] = s_out[bsl * OPAD + vl];
            }
        }
    }
}

// ---------------------------------------------------------------------------
extern "C" void kernel_launch(void* const* d_in, const int* in_sizes, int n_in,
                              void* d_out, int out_size)
{
    (void)in_sizes; (void)n_in; (void)out_size;
    const float* scales     = (const float*)d_in[0];
    const float* transforms = (const float*)d_in[1];
    const float* pw         = (const float*)d_in[2];
    const float* off        = (const float*)d_in[3];
    const float* base       = (const float*)d_in[4];
    float* out = (float*)d_out;

    cudaFuncSetAttribute(prep_kernel,
                         cudaFuncAttributeMaxDynamicSharedMemorySize, PREP_SMEM);
    prep_kernel<<<NDEF + NROT, 128, PREP_SMEM>>>(off, base, scales, transforms, pw);

    cudaFuncSetAttribute(mesh_gemm_kernel,
                         cudaFuncAttributeMaxDynamicSharedMemorySize, SMEM_BYTES);
    dim3 grid((V_N + M_T - 1) / M_T, 6);   // (21, 6) = 126 CTAs, 1 per SM
    mesh_gemm_kernel<<<grid, 512, SMEM_BYTES>>>(out);
}

// round 17
// speedup vs baseline: 1.2481x; 1.0210x over previous
#include <cuda_runtime.h>
#include <cuda_fp16.h>
#include <cstdint>

#define B_S   256
#define P_N   64
#define V_N   2562
#define VPAD  2688          // 21*128, zero-padded tail rows
#define KP    192           // K' = 192 (fp16); translation handled in epilogue
#define M_T   128
#define N_T   128
#define VTP   16            // defsplit v-tile
#define NDEF  161           // ceil(2562/16)
#define NROT  128           // rot blocks (2 bs each)
#define ROWS2 200           // padded prep staging row stride (fp16)
#define PL    16384u        // one 64-col plane: 128 rows x 128B

// ---- scratch (zero-initialized device globals; no runtime alloc) ----
__device__ __align__(16) __half g_def[(size_t)VPAD * KP];     // ~1.0MB
__device__ __align__(16) __half g_B[(size_t)3 * B_S * KP];    // ~0.3MB
__device__ float g_T[3 * B_S];                                // translations

__device__ __forceinline__ uint32_t smem_u32(const void* p) {
    uint32_t a;
    asm("{ .reg .u64 t; cvta.to.shared.u64 t, %1; cvt.u32.u64 %0, t; }" : "=r"(a) : "l"(p));
    return a;
}
__device__ __forceinline__ uint32_t sw128(uint32_t x) { return x ^ ((x >> 3) & 0x70); }

#define CP16(dst, src) \
    asm volatile("cp.async.cg.shared.global [%0], [%1], 16;" :: "r"(dst), "l"(src))
#define CP_COMMIT() asm volatile("cp.async.commit_group;" ::: "memory")
#define CP_WAITN(n) asm volatile("cp.async.wait_group " #n ";" ::: "memory")

#define LDSM4(r, addr) \
    asm volatile("ldmatrix.sync.aligned.m8n8.x4.shared.b16 {%0,%1,%2,%3}, [%4];" \
        : "=r"((r)[0]), "=r"((r)[1]), "=r"((r)[2]), "=r"((r)[3]) : "r"(addr))

#define MMA(d, a, b0, b1) \
    asm volatile("mma.sync.aligned.m16n8k16.row.col.f32.f16.f16.f32 " \
        "{%0,%1,%2,%3}, {%4,%5,%6,%7}, {%8,%9}, {%0,%1,%2,%3};" \
        : "+f"((d)[0]), "+f"((d)[1]), "+f"((d)[2]), "+f"((d)[3]) \
        : "r"((a)[0]), "r"((a)[1]), "r"((a)[2]), "r"((a)[3]), "r"(b0), "r"(b1))

// ---------------------------------------------------------------------------
// Fused prep. Blocks [0,NDEF): defsplit (A-hat rows); rest: rot (B-hat + g_T).
// ---------------------------------------------------------------------------
#define PREP_SMEM (VTP * ROWS2 * 2 + 256)

__global__ __launch_bounds__(128) void prep_kernel(
    const float* __restrict__ off,
    const float* __restrict__ base,
    const float* __restrict__ scales,
    const float* __restrict__ transforms,
    const float* __restrict__ pw)
{
    extern __shared__ __align__(16) char smem[];
    const int tid = threadIdx.x;

    if (blockIdx.x < NDEF) {
        __half* s_row = (__half*)smem;                      // [VTP][ROWS2]
        float* s_base = (float*)(smem + VTP * ROWS2 * 2);   // [48]
        const int v0 = blockIdx.x * VTP;
        const int nv3 = min(VTP * 3, (V_N - v0) * 3);

        for (int i = tid; i < (VTP * ROWS2) / 8; i += 128)
            ((uint4*)s_row)[i] = make_uint4(0, 0, 0, 0);
        if (tid < VTP * 3)
            s_base[tid] = (v0 * 3 + tid < V_N * 3) ? base[v0 * 3 + tid] : 0.f;
        __syncthreads();

        for (int idx = tid; idx < P_N * 24; idx += 128) {
            const int p = idx / 24, q = idx - p * 24;
            const int f0 = 2 * q;
            float e[2];
            if (f0 + 1 < nv3) {
                const float2 d = *(const float2*)(off + ((size_t)p * V_N + v0) * 3 + f0);
                e[0] = d.x; e[1] = d.y;
            } else {
                e[0] = (f0 < nv3) ? off[((size_t)p * V_N + v0) * 3 + f0] : 0.f;
                e[1] = 0.f;
            }
            #pragma unroll
            for (int t = 0; t < 2; ++t) {
                const int f = f0 + t;
                const int vl = f / 3, j = f - 3 * vl;
                s_row[vl * ROWS2 + p * 3 + j] = __float2half(e[t] + s_base[f]);
            }
        }
        __syncthreads();

        // coalesced write-out: 16 rows x 24 uint4 (192 fp16)
        for (int i = tid; i < VTP * 24; i += 128) {
            const int row = i / 24, u = i - row * 24;
            *(uint4*)(g_def + (size_t)(v0 + row) * KP + u * 8) =
                ((const uint4*)(s_row + row * ROWS2))[u];
        }
    } else {
        const int bs = (blockIdx.x - NDEF) * 2 + (tid >> 6);
        const int p  = tid & 63;

        const float* t = transforms + ((size_t)bs * P_N + p) * 6;
        const float w  = pw[bs * P_N + p];
        const float ws = w * scales[bs];

        float sx, cx, sy, cy, sz, cz;
        sincosf(t[3], &sx, &cx);
        sincosf(t[4], &sy, &cy);
        sincosf(t[5], &sz, &cz);

        float m[9];
        m[0] = cy*cz;            m[1] = -cy*sz;           m[2] = sy;
        m[3] = cx*sz + sx*sy*cz; m[4] = cx*cz - sx*sy*sz; m[5] = -sx*cy;
        m[6] = sx*sz - cx*sy*cz; m[7] = sx*cz + cx*sy*sz; m[8] = cx*cy;

        #pragma unroll
        for (int i = 0; i < 3; ++i) {
            __half* row = g_B + ((size_t)i * B_S + bs) * KP;
            #pragma unroll
            for (int j = 0; j < 3; ++j)
                row[p * 3 + j] = __float2half(m[i * 3 + j] * ws);
        }

        float* red = (float*)smem;   // [128][4]
        red[tid * 4 + 0] = w * t[0];
        red[tid * 4 + 1] = w * t[1];
        red[tid * 4 + 2] = w * t[2];
        __syncthreads();
        if (p < 3) {
            const int b0 = (tid >> 6) * 64;
            float s = 0.f;
            for (int q = 0; q < 64; ++q) s += red[(b0 + q) * 4 + p];
            g_T[p * B_S + bs] = s;
        }
    }
}

// ---------------------------------------------------------------------------
// GEMM: 3 planes, cascaded cp.async (compute plane 0 while 1,2 land),
// 12 k-steps, smem-transposed epilogue adding fp32 translation.
// Grid (21,6) = 126 CTAs, 1/SM, 512 threads (4x4 warps of 32x32).
// ---------------------------------------------------------------------------
#define A_OFF 0u
#define B_OFF 49152u
#define TR_OFF 98304u
#define SMEM_BYTES (98304 + 640)
#define OPAD  132           // s_out row stride in floats

__global__ __launch_bounds__(512, 1) void mesh_gemm_kernel(float* __restrict__ out)
{
    extern __shared__ __align__(1024) char smem[];
    const uint32_t sbase = smem_u32(smem);
    const int tid  = threadIdx.x;
    const int lane = tid & 31;
    const int warp = tid >> 5;                 // 0..15
    const int v0   = blockIdx.x * M_T;
    const int nb   = blockIdx.y;
    const int i_   = nb >> 1;                  // output component (0..2)
    const int bs0  = (nb & 1) * N_T;
    const int bRow0 = i_ * B_S + bs0;

    // ---- 1) cascaded loads: one commit group per plane ----
    {
        const int sRow = tid >> 3, sU = (tid & 7) * 16;
        #pragma unroll
        for (int c = 0; c < 3; ++c) {
            #pragma unroll
            for (int it = 0; it < 2; ++it) {
                const int row = sRow + it * 64;
                CP16(sbase + A_OFF + c * PL + sw128(row * 128 + sU),
                     g_def + ((size_t)(v0 + row) * KP + c * 64) + sU / 2);
                CP16(sbase + B_OFF + c * PL + sw128(row * 128 + sU),
                     g_B + ((size_t)(bRow0 + row) * KP + c * 64) + sU / 2);
            }
            CP_COMMIT();
        }
    }
    // stage translations (fp32, 128 values)
    float* s_trans = (float*)(smem + TR_OFF);
    if (tid < N_T) s_trans[tid] = g_T[i_ * B_S + bs0 + tid];

    // ---- 2) compute, one plane per wait level ----
    const int wm = warp & 3;
    const int wn = warp >> 2;
    const int rowA  = wm * 32 + (lane & 7) + ((lane >> 3) & 1) * 8;
    const int kselA = ((lane >> 4) & 1) * 16;
    const int rowB  = wn * 32 + ((lane >> 4) & 1) * 8 + (lane & 7);
    const int kselB = ((lane >> 3) & 1) * 16;

    float acc[2][4][4];
    #pragma unroll
    for (int mt = 0; mt < 2; ++mt)
        #pragma unroll
        for (int nt = 0; nt < 4; ++nt)
            #pragma unroll
            for (int e = 0; e < 4; ++e) acc[mt][nt][e] = 0.f;

    #define COMPUTE_PLANE(c) do {                                              \
        const uint32_t sA = sbase + A_OFF + (c) * PL;                          \
        const uint32_t sB = sbase + B_OFF + (c) * PL;                          \
        _Pragma("unroll")                                                      \
        for (int ks = 0; ks < 4; ++ks) {                                       \
            uint32_t a0[4], a1[4], q0[4], q1[4];                               \
            LDSM4(a0, sA + sw128(rowA * 128 + ks * 32 + kselA));               \
            LDSM4(a1, sA + sw128((rowA + 16) * 128 + ks * 32 + kselA));        \
            LDSM4(q0, sB + sw128(rowB * 128 + ks * 32 + kselB));               \
            LDSM4(q1, sB + sw128((rowB + 16) * 128 + ks * 32 + kselB));        \
            MMA(acc[0][0], a0, q0[0], q0[1]);  MMA(acc[0][1], a0, q0[2], q0[3]); \
            MMA(acc[0][2], a0, q1[0], q1[1]);  MMA(acc[0][3], a0, q1[2], q1[3]); \
            MMA(acc[1][0], a1, q0[0], q0[1]);  MMA(acc[1][1], a1, q0[2], q0[3]); \
            MMA(acc[1][2], a1, q1[0], q1[1]);  MMA(acc[1][3], a1, q1[2], q1[3]); \
        }                                                                      \
    } while (0)

    CP_WAITN(2); __syncthreads();
    COMPUTE_PLANE(0);
    CP_WAITN(1); __syncthreads();
    COMPUTE_PLANE(1);
    CP_WAITN(0); __syncthreads();
    COMPUTE_PLANE(2);
    __syncthreads();   // all smem reads done; reuse as s_out

    // ---- 3) stage accs into s_out[bs][v] ----
    float* s_out = (float*)smem;   // 128 x OPAD floats = 67.6KB
    {
        const int g  = lane >> 2;
        const int cq = lane & 3;
        #pragma unroll
        for (int mt = 0; mt < 2; ++mt) {
            const int vA = wm * 32 + mt * 16 + g;
            const int vB = vA + 8;
            #pragma unroll
            for (int nt = 0; nt < 4; ++nt) {
                const int bs = wn * 32 + nt * 8 + 2 * cq;
                s_out[bs * OPAD + vA]       = acc[mt][nt][0];
                s_out[(bs + 1) * OPAD + vA] = acc[mt][nt][1];
                s_out[bs * OPAD + vB]       = acc[mt][nt][2];
                s_out[(bs + 1) * OPAD + vB] = acc[mt][nt][3];
            }
        }
    }
    __syncthreads();

    // ---- 4) stores: warp per bs row, lane = consecutive v, + translation ----
    {
        const int nv = min(M_T, V_N - v0);
        #pragma unroll
        for (int r = 0; r < 8; ++r) {
            const int bsl = warp + r * 16;
            const float tr = s_trans[bsl];
            const size_t obase = ((size_t)(bs0 + bsl) * V_N + v0) * 3 + i_;
            #pragma unroll
            for (int k = 0; k < 4; ++k) {
                const int vl = lane + k * 32;
                if (vl < nv)
                    out[obase + (size_t)vl * 3] = s_out[bsl * OPAD + vl] + tr;
            }
        }
    }
}

// ---------------------------------------------------------------------------
extern "C" void kernel_launch(void* const* d_in, const int* in_sizes, int n_in,
                              void* d_out, int out_size)
{
    (void)in_sizes; (void)n_in; (void)out_size;
    const float* scales     = (const float*)d_in[0];
    const float* transforms = (const float*)d_in[1];
    const float* pw         = (const float*)d_in[2];
    const float* off        = (const float*)d_in[3];
    const float* base       = (const float*)d_in[4];
    float* out = (float*)d_out;

    cudaFuncSetAttribute(prep_kernel,
                         cudaFuncAttributeMaxDynamicSharedMemorySize, PREP_SMEM);
    prep_kernel<<<NDEF + NROT, 128, PREP_SMEM>>>(off, base, scales, transforms, pw);

    cudaFuncSetAttribute(mesh_gemm_kernel,
                         cudaFuncAttributeMaxDynamicSharedMemorySize, SMEM_BYTES);
    dim3 grid((V_N + M_T - 1) / M_T, 6);   // (21, 6) = 126 CTAs, 1 per SM
    mesh_gemm_kernel<<<grid, 512, SMEM_BYTES>>>(out);
}